// round 14
// baseline (speedup 1.0000x reference)
#include <cuda_runtime.h>
#include <cuda_bf16.h>
#include <cstdint>

#define NROWS 16384
#define DD    128
#define BM    64
#define BN    128
#define KSPLIT 4
#define TILES_PER (NROWS / BN / KSPLIT)   // 32
#define NTHREADS 128

// device globals (allocation-free rule)
__device__ __nv_bfloat16 g_nx[NROWS * DD];            // normalized rows (K == V base)
__device__ float         g_norm[NROWS];               // row norms
__device__ float         g_opart[KSPLIT][NROWS][DD];  // split-K O partials
__device__ float         g_dpart[KSPLIT][NROWS];      // split-K den partials

// ---------------------------------------------------------------------------
__device__ __forceinline__ uint32_t smem_u32(const void* p) {
    uint32_t a;
    asm("{ .reg .u64 t; cvta.to.shared.u64 t, %1; cvt.u32.u64 %0, t; }"
        : "=r"(a) : "l"(p));
    return a;
}
__device__ __forceinline__ void cpa16(uint32_t dst, const void* src) {
    asm volatile("cp.async.cg.shared.global [%0], [%1], 16;"
                 :: "r"(dst), "l"(src) : "memory");
}
#define CP_COMMIT() asm volatile("cp.async.commit_group;" ::: "memory")
#define CP_WAIT1()  asm volatile("cp.async.wait_group 1;" ::: "memory")
#define CP_WAIT0()  asm volatile("cp.async.wait_group 0;" ::: "memory")

__device__ __forceinline__ void ldsm4(uint32_t* r, uint32_t addr) {
    asm volatile("ldmatrix.sync.aligned.m8n8.x4.shared.b16 {%0,%1,%2,%3}, [%4];"
        : "=r"(r[0]), "=r"(r[1]), "=r"(r[2]), "=r"(r[3]) : "r"(addr));
}
__device__ __forceinline__ void ldsm4t(uint32_t* r, uint32_t addr) {
    asm volatile("ldmatrix.sync.aligned.m8n8.x4.trans.shared.b16 {%0,%1,%2,%3}, [%4];"
        : "=r"(r[0]), "=r"(r[1]), "=r"(r[2]), "=r"(r[3]) : "r"(addr));
}
__device__ __forceinline__ void mma16816(float* c, const uint32_t* a,
                                         uint32_t b0, uint32_t b1) {
    asm volatile("mma.sync.aligned.m16n8k16.row.col.f32.bf16.bf16.f32 "
        "{%0,%1,%2,%3}, {%4,%5,%6,%7}, {%8,%9}, {%0,%1,%2,%3};"
        : "+f"(c[0]), "+f"(c[1]), "+f"(c[2]), "+f"(c[3])
        : "r"(a[0]), "r"(a[1]), "r"(a[2]), "r"(a[3]), "r"(b0), "r"(b1));
}
__device__ __forceinline__ uint32_t packbf(float lo, float hi) {
    uint32_t d;
    asm("cvt.rn.bf16x2.f32 %0, %1, %2;" : "=r"(d) : "f"(hi), "f"(lo));
    return d;
}
// Degree-7 Taylor exp, s in [-1,1]: rel err < 3e-5, pure FFMA
__device__ __forceinline__ float expp(float s) {
    float p = 1.9841270e-4f;
    p = fmaf(p, s, 1.3888889e-3f);
    p = fmaf(p, s, 8.3333333e-3f);
    p = fmaf(p, s, 4.1666667e-2f);
    p = fmaf(p, s, 1.6666667e-1f);
    p = fmaf(p, s, 0.5f);
    p = fmaf(p, s, 1.0f);
    p = fmaf(p, s, 1.0f);
    return p;
}
// Tile smem layout: row r (0..127) * 256B, 16B chunk c swizzled by row
__device__ __forceinline__ uint32_t toff(int r, int c) {
    return (uint32_t)(r * 256 + ((c ^ (r & 7)) << 4));
}

#define STG_NX(s) ((s) * 32768)
#define STG_KN(s) (65536 + (s) * 512)
#define SMEM_BYTES (65536 + 1024)

// ---------------------------------------------------------------------------
__global__ void prep_kernel(const float* __restrict__ x) {
    int row  = blockIdx.x * 8 + (threadIdx.x >> 5);
    int lane = threadIdx.x & 31;
    float4 v = *(const float4*)(x + (size_t)row * DD + lane * 4);
    float ss = v.x * v.x + v.y * v.y + v.z * v.z + v.w * v.w;
    #pragma unroll
    for (int o = 16; o; o >>= 1) ss += __shfl_xor_sync(0xffffffffu, ss, o);
    float nrm = sqrtf(ss);
    float inv = 1.0f / fmaxf(nrm, 1e-12f);
    size_t base = (size_t)row * DD + lane * 4;
    *(__nv_bfloat162*)(g_nx + base)     = __floats2bfloat162_rn(v.x * inv, v.y * inv);
    *(__nv_bfloat162*)(g_nx + base + 2) = __floats2bfloat162_rn(v.z * inv, v.w * inv);
    if (lane == 0) g_norm[row] = nrm;
}

// ---------------------------------------------------------------------------
__device__ __forceinline__ void prefetch_tile(int tt, int tend, uint32_t sb, int tid) {
    if (tt < tend) {
        uint32_t nb = sb + STG_NX(tt & 1);
        int j0 = tt * BN;
        #pragma unroll
        for (int i = 0; i < 16; i++) {
            int idx = tid + i * NTHREADS;
            int r = idx >> 4, c = idx & 15;
            cpa16(nb + toff(r, c), g_nx + (size_t)(j0 + r) * DD + c * 8);
        }
        if (tid < 32)
            cpa16(sb + STG_KN(tt & 1) + tid * 16, g_norm + j0 + tid * 4);
    }
    CP_COMMIT();
}

// ---------------------------------------------------------------------------
// Split-K attention partial. BM=64, 4 warps, 3 CTAs/SM.
// Half-phase body: 4 S-groups -> exp -> 4 V-steps, pk[16] live (no spills
// at the 170-reg cap), 32-64-long MMA streams.
// ---------------------------------------------------------------------------
__global__ __launch_bounds__(NTHREADS, 3)
void attn_kernel() {
    extern __shared__ char smem[];
    uint32_t sb = smem_u32(smem);
    const int tid  = threadIdx.x;
    const int wid  = tid >> 5;
    const int lane = tid & 31;
    const int qt   = blockIdx.x >> 2;
    const int half = blockIdx.x & 3;
    const int i0   = qt * BM;
    const int t0   = half * TILES_PER;
    const int tend = t0 + TILES_PER;

    // ---- stage Q tile (64 rows) into stage-(t0&1) area, load Q fragments ----
    {
        uint32_t qb = sb + STG_NX(t0 & 1);
        #pragma unroll
        for (int i = 0; i < 8; i++) {
            int idx = tid + i * NTHREADS;
            int r = idx >> 4, c = idx & 15;
            cpa16(qb + toff(r, c), g_nx + (size_t)(i0 + r) * DD + c * 8);
        }
        CP_COMMIT(); CP_WAIT0();
    }
    __syncthreads();

    uint32_t q[8][4];
    {
        int rbase = wid * 16 + (lane & 7) + ((lane >> 3) & 1) * 8;
        #pragma unroll
        for (int kk = 0; kk < 8; kk++)
            ldsm4(q[kk], sb + STG_NX(t0 & 1) + toff(rbase, 2 * kk + (lane >> 4)));
    }
    __syncthreads();

    prefetch_tile(t0, tend, sb, tid);
    prefetch_tile(t0 + 1, tend, sb, tid);

    float o[16][4];
    #pragma unroll
    for (int j = 0; j < 16; j++)
        #pragma unroll
        for (int c = 0; c < 4; c++) o[j][c] = 0.0f;
    float den0 = 0.0f, den1 = 0.0f;

    const int klr = lane & 7;
    const int kg1 = (lane >> 3) & 1;
    const int kg2 = lane >> 4;
    const int jq  = 2 * (lane & 3);

    for (int t = t0; t < tend; t++) {
        uint32_t nb  = sb + STG_NX(t & 1);
        uint32_t knb = sb + STG_KN(t & 1);
        CP_WAIT1();
        __syncthreads();

        // ---- two half-phases per tile: (4 S-groups -> exp) -> (4 V-steps) ----
        #pragma unroll
        for (int hp = 0; hp < 2; hp++) {
            uint32_t pk[16];
            #pragma unroll
            for (int gi = 0; gi < 4; gi++) {
                const int g = hp * 4 + gi;
                float s0[4] = {0, 0, 0, 0}, s1[4] = {0, 0, 0, 0};
                int krow = g * 16 + kg2 * 8 + klr;
                #pragma unroll
                for (int kk = 0; kk < 8; kk++) {
                    uint32_t b[4];
                    ldsm4(b, nb + toff(krow, 2 * kk + kg1));
                    mma16816(s0, q[kk], b[0], b[1]);
                    mma16816(s1, q[kk], b[2], b[3]);
                }
                float e00 = expp(s0[0]), e01 = expp(s0[1]);
                float e02 = expp(s0[2]), e03 = expp(s0[3]);
                float e10 = expp(s1[0]), e11 = expp(s1[1]);
                float e12 = expp(s1[2]), e13 = expp(s1[3]);
                den0 += e00 + e01 + e10 + e11;
                den1 += e02 + e03 + e12 + e13;
                float2 kn01, kn89;
                asm("ld.shared.v2.f32 {%0,%1}, [%2];" : "=f"(kn01.x), "=f"(kn01.y)
                    : "r"(knb + (g * 16 + jq) * 4));
                asm("ld.shared.v2.f32 {%0,%1}, [%2];" : "=f"(kn89.x), "=f"(kn89.y)
                    : "r"(knb + (g * 16 + 8 + jq) * 4));
                pk[4 * gi + 0] = packbf(e00 * kn01.x, e01 * kn01.y);
                pk[4 * gi + 1] = packbf(e02 * kn01.x, e03 * kn01.y);
                pk[4 * gi + 2] = packbf(e10 * kn89.x, e11 * kn89.y);
                pk[4 * gi + 3] = packbf(e12 * kn89.x, e13 * kn89.y);
            }
            #pragma unroll
            for (int ki = 0; ki < 4; ki++) {
                const int kk = hp * 4 + ki;
                int vrow = kk * 16 + kg1 * 8 + klr;
                #pragma unroll
                for (int dg = 0; dg < 8; dg++) {
                    uint32_t v[4];
                    ldsm4t(v, nb + toff(vrow, 2 * dg + kg2));
                    mma16816(o[2 * dg],     &pk[4 * ki], v[0], v[1]);
                    mma16816(o[2 * dg + 1], &pk[4 * ki], v[2], v[3]);
                }
            }
        }

        __syncthreads();
        prefetch_tile(t + 2, tend, sb, tid);
    }

    // ---- write partials: den (quad-reduced) + O frags ----
    den0 += __shfl_xor_sync(0xffffffffu, den0, 1);
    den0 += __shfl_xor_sync(0xffffffffu, den0, 2);
    den1 += __shfl_xor_sync(0xffffffffu, den1, 1);
    den1 += __shfl_xor_sync(0xffffffffu, den1, 2);

    const int ra = i0 + wid * 16 + (lane >> 2);
    if ((lane & 3) == 0) {
        g_dpart[half][ra]     = den0;
        g_dpart[half][ra + 8] = den1;
    }
    #pragma unroll
    for (int j = 0; j < 16; j++) {
        int col = 8 * j + jq;
        *(float2*)&g_opart[half][ra][col]     = make_float2(o[j][0], o[j][1]);
        *(float2*)&g_opart[half][ra + 8][col] = make_float2(o[j][2], o[j][3]);
    }
}

// ---------------------------------------------------------------------------
// Epilogue: combine KSPLIT partials, y = 1.5x - 0.5*O/den, LayerNorm.
// ---------------------------------------------------------------------------
__global__ __launch_bounds__(256)
void ln_kernel(const float* __restrict__ x,
               const float* __restrict__ gamma,
               const float* __restrict__ beta,
               float* __restrict__ out) {
    const int row  = blockIdx.x * 8 + (threadIdx.x >> 5);
    const int lane = threadIdx.x & 31;
    const int c    = lane * 4;

    float4 oa = *(const float4*)&g_opart[0][row][c];
    float den = g_dpart[0][row];
    #pragma unroll
    for (int h = 1; h < KSPLIT; h++) {
        float4 ob = *(const float4*)&g_opart[h][row][c];
        oa.x += ob.x; oa.y += ob.y; oa.z += ob.z; oa.w += ob.w;
        den += g_dpart[h][row];
    }
    const float inv = 0.5f / den;   // folds SCALE=-0.5
    float4 xv = *(const float4*)(x + (size_t)row * DD + c);

    float y0 = fmaf(1.5f, xv.x, -oa.x * inv);
    float y1 = fmaf(1.5f, xv.y, -oa.y * inv);
    float y2 = fmaf(1.5f, xv.z, -oa.z * inv);
    float y3 = fmaf(1.5f, xv.w, -oa.w * inv);

    float s1 = y0 + y1 + y2 + y3;
    float s2 = fmaf(y0, y0, fmaf(y1, y1, fmaf(y2, y2, y3 * y3)));
    #pragma unroll
    for (int o = 16; o; o >>= 1) {
        s1 += __shfl_xor_sync(0xffffffffu, s1, o);
        s2 += __shfl_xor_sync(0xffffffffu, s2, o);
    }
    const float mu   = s1 * (1.0f / DD);
    const float var  = s2 * (1.0f / DD) - mu * mu;
    const float rstd = rsqrtf(var + 1e-5f);

    float4 gm = *(const float4*)(gamma + c);
    float4 bt = *(const float4*)(beta + c);
    float4 r;
    r.x = fmaf((y0 - mu) * rstd, gm.x, bt.x);
    r.y = fmaf((y1 - mu) * rstd, gm.y, bt.y);
    r.z = fmaf((y2 - mu) * rstd, gm.z, bt.z);
    r.w = fmaf((y3 - mu) * rstd, gm.w, bt.w);
    *(float4*)(out + (size_t)row * DD + c) = r;
}

// ---------------------------------------------------------------------------
extern "C" void kernel_launch(void* const* d_in, const int* in_sizes, int n_in,
                              void* d_out, int out_size) {
    const float* x     = (const float*)d_in[0];
    const float* gamma = (const float*)d_in[1];
    const float* beta  = (const float*)d_in[2];
    float* out = (float*)d_out;

    prep_kernel<<<NROWS / 8, 256>>>(x);

    cudaFuncSetAttribute(attn_kernel,
                         cudaFuncAttributeMaxDynamicSharedMemorySize, SMEM_BYTES);
    attn_kernel<<<(NROWS / BM) * KSPLIT, NTHREADS, SMEM_BYTES>>>();

    ln_kernel<<<NROWS / 8, 256>>>(x, gamma, beta, out);
}

// round 16
// speedup vs baseline: 1.0402x; 1.0402x over previous
#include <cuda_runtime.h>
#include <cuda_bf16.h>
#include <cstdint>

#define NROWS 16384
#define DD    128
#define BM    64
#define BN    128
#define NTILES (NROWS / BN)
#define NTHREADS 128

// device globals (allocation-free rule)
__device__ __nv_bfloat16 g_nx[NROWS * DD];   // normalized rows (K == V base)
__device__ float         g_norm[NROWS];      // row norms

// ---------------------------------------------------------------------------
__device__ __forceinline__ uint32_t smem_u32(const void* p) {
    uint32_t a;
    asm("{ .reg .u64 t; cvta.to.shared.u64 t, %1; cvt.u32.u64 %0, t; }"
        : "=r"(a) : "l"(p));
    return a;
}
__device__ __forceinline__ void cpa16(uint32_t dst, const void* src) {
    asm volatile("cp.async.cg.shared.global [%0], [%1], 16;"
                 :: "r"(dst), "l"(src) : "memory");
}
#define CP_COMMIT() asm volatile("cp.async.commit_group;" ::: "memory")
#define CP_WAIT1()  asm volatile("cp.async.wait_group 1;" ::: "memory")
#define CP_WAIT0()  asm volatile("cp.async.wait_group 0;" ::: "memory")

__device__ __forceinline__ void ldsm4(uint32_t* r, uint32_t addr) {
    asm volatile("ldmatrix.sync.aligned.m8n8.x4.shared.b16 {%0,%1,%2,%3}, [%4];"
        : "=r"(r[0]), "=r"(r[1]), "=r"(r[2]), "=r"(r[3]) : "r"(addr));
}
__device__ __forceinline__ void ldsm4t(uint32_t* r, uint32_t addr) {
    asm volatile("ldmatrix.sync.aligned.m8n8.x4.trans.shared.b16 {%0,%1,%2,%3}, [%4];"
        : "=r"(r[0]), "=r"(r[1]), "=r"(r[2]), "=r"(r[3]) : "r"(addr));
}
__device__ __forceinline__ void mma16816(float* c, const uint32_t* a,
                                         uint32_t b0, uint32_t b1) {
    asm volatile("mma.sync.aligned.m16n8k16.row.col.f32.bf16.bf16.f32 "
        "{%0,%1,%2,%3}, {%4,%5,%6,%7}, {%8,%9}, {%0,%1,%2,%3};"
        : "+f"(c[0]), "+f"(c[1]), "+f"(c[2]), "+f"(c[3])
        : "r"(a[0]), "r"(a[1]), "r"(a[2]), "r"(a[3]), "r"(b0), "r"(b1));
}
__device__ __forceinline__ uint32_t packbf(float lo, float hi) {
    uint32_t d;
    asm("cvt.rn.bf16x2.f32 %0, %1, %2;" : "=r"(d) : "f"(hi), "f"(lo));
    return d;
}
// Degree-7 Taylor exp, s in [-1,1]: rel err < 3e-5, pure FFMA
__device__ __forceinline__ float expp(float s) {
    float p = 1.9841270e-4f;
    p = fmaf(p, s, 1.3888889e-3f);
    p = fmaf(p, s, 8.3333333e-3f);
    p = fmaf(p, s, 4.1666667e-2f);
    p = fmaf(p, s, 1.6666667e-1f);
    p = fmaf(p, s, 0.5f);
    p = fmaf(p, s, 1.0f);
    p = fmaf(p, s, 1.0f);
    return p;
}
// Tile smem layout: row r (0..127) * 256B, 16B chunk c swizzled by row
__device__ __forceinline__ uint32_t toff(int r, int c) {
    return (uint32_t)(r * 256 + ((c ^ (r & 7)) << 4));
}

#define STG_NX(s) ((s) * 32768)
#define STG_KN(s) (65536 + (s) * 512)
#define SMEM_BYTES (65536 + 1024)

// ---------------------------------------------------------------------------
__global__ void prep_kernel(const float* __restrict__ x) {
    int row  = blockIdx.x * 8 + (threadIdx.x >> 5);
    int lane = threadIdx.x & 31;
    float4 v = *(const float4*)(x + (size_t)row * DD + lane * 4);
    float ss = v.x * v.x + v.y * v.y + v.z * v.z + v.w * v.w;
    #pragma unroll
    for (int o = 16; o; o >>= 1) ss += __shfl_xor_sync(0xffffffffu, ss, o);
    float nrm = sqrtf(ss);
    float inv = 1.0f / fmaxf(nrm, 1e-12f);
    size_t base = (size_t)row * DD + lane * 4;
    *(__nv_bfloat162*)(g_nx + base)     = __floats2bfloat162_rn(v.x * inv, v.y * inv);
    *(__nv_bfloat162*)(g_nx + base + 2) = __floats2bfloat162_rn(v.z * inv, v.w * inv);
    if (lane == 0) g_norm[row] = nrm;
}

// ---------------------------------------------------------------------------
__device__ __forceinline__ void prefetch_tile(int t, uint32_t sb, int tid) {
    if (t < NTILES) {
        uint32_t nb = sb + STG_NX(t & 1);
        int j0 = t * BN;
        #pragma unroll
        for (int i = 0; i < 16; i++) {
            int idx = tid + i * NTHREADS;
            int r = idx >> 4, c = idx & 15;
            cpa16(nb + toff(r, c), g_nx + (size_t)(j0 + r) * DD + c * 8);
        }
        if (tid < 32)
            cpa16(sb + STG_KN(t & 1) + tid * 16, g_norm + j0 + tid * 4);
    }
    CP_COMMIT();
}

// ---------------------------------------------------------------------------
// Fused attention + LayerNorm. BM=64, 4 warps, 2 CTAs/SM.
// Half-phase inner loop with paired key-groups: 4 independent S-MMA chains
// per warp (vs 2 in round 7) to cover HMMA latency; pk[16] live only.
// ---------------------------------------------------------------------------
__global__ __launch_bounds__(NTHREADS, 2)
void attn_kernel(const float* __restrict__ x,
                 const float* __restrict__ gamma,
                 const float* __restrict__ beta,
                 float* __restrict__ out) {
    extern __shared__ char smem[];
    uint32_t sb = smem_u32(smem);
    const int tid  = threadIdx.x;
    const int wid  = tid >> 5;
    const int lane = tid & 31;
    const int i0   = blockIdx.x * BM;

    // ---- stage Q tile (64 rows) into stage0 area, load Q fragments ----
    {
        uint32_t qb = sb + STG_NX(0);
        #pragma unroll
        for (int i = 0; i < 8; i++) {
            int idx = tid + i * NTHREADS;
            int r = idx >> 4, c = idx & 15;
            cpa16(qb + toff(r, c), g_nx + (size_t)(i0 + r) * DD + c * 8);
        }
        CP_COMMIT(); CP_WAIT0();
    }
    __syncthreads();

    uint32_t q[8][4];
    {
        int rbase = wid * 16 + (lane & 7) + ((lane >> 3) & 1) * 8;
        #pragma unroll
        for (int kk = 0; kk < 8; kk++)
            ldsm4(q[kk], sb + STG_NX(0) + toff(rbase, 2 * kk + (lane >> 4)));
    }
    __syncthreads();

    prefetch_tile(0, sb, tid);
    prefetch_tile(1, sb, tid);

    float o[16][4];
    #pragma unroll
    for (int j = 0; j < 16; j++)
        #pragma unroll
        for (int c = 0; c < 4; c++) o[j][c] = 0.0f;
    float den0 = 0.0f, den1 = 0.0f;

    const int klr = lane & 7;
    const int kg1 = (lane >> 3) & 1;
    const int kg2 = lane >> 4;
    const int jq  = 2 * (lane & 3);

    for (int t = 0; t < NTILES; t++) {
        uint32_t nb  = sb + STG_NX(t & 1);
        uint32_t knb = sb + STG_KN(t & 1);
        CP_WAIT1();
        __syncthreads();

        // ---- two half-phases; each: 2 group-pairs (4 S chains) + 4 V-steps ----
        #pragma unroll
        for (int hp = 0; hp < 2; hp++) {
            uint32_t pk[16];
            #pragma unroll
            for (int gp = 0; gp < 2; gp++) {
                const int g0 = hp * 4 + gp * 2;
                float sA0[4] = {0,0,0,0}, sA1[4] = {0,0,0,0};
                float sB0[4] = {0,0,0,0}, sB1[4] = {0,0,0,0};
                int krow0 = g0 * 16 + kg2 * 8 + klr;
                int krow1 = krow0 + 16;
                #pragma unroll
                for (int kk = 0; kk < 8; kk++) {
                    uint32_t bA[4], bB[4];
                    ldsm4(bA, nb + toff(krow0, 2 * kk + kg1));
                    ldsm4(bB, nb + toff(krow1, 2 * kk + kg1));
                    mma16816(sA0, q[kk], bA[0], bA[1]);
                    mma16816(sA1, q[kk], bA[2], bA[3]);
                    mma16816(sB0, q[kk], bB[0], bB[1]);
                    mma16816(sB1, q[kk], bB[2], bB[3]);
                }
                // exp + fold key norm + pack, group A (g0)
                {
                    float e00 = expp(sA0[0]), e01 = expp(sA0[1]);
                    float e02 = expp(sA0[2]), e03 = expp(sA0[3]);
                    float e10 = expp(sA1[0]), e11 = expp(sA1[1]);
                    float e12 = expp(sA1[2]), e13 = expp(sA1[3]);
                    den0 += e00 + e01 + e10 + e11;
                    den1 += e02 + e03 + e12 + e13;
                    float2 kn01, kn89;
                    asm("ld.shared.v2.f32 {%0,%1}, [%2];" : "=f"(kn01.x), "=f"(kn01.y)
                        : "r"(knb + (g0 * 16 + jq) * 4));
                    asm("ld.shared.v2.f32 {%0,%1}, [%2];" : "=f"(kn89.x), "=f"(kn89.y)
                        : "r"(knb + (g0 * 16 + 8 + jq) * 4));
                    pk[8 * gp + 0] = packbf(e00 * kn01.x, e01 * kn01.y);
                    pk[8 * gp + 1] = packbf(e02 * kn01.x, e03 * kn01.y);
                    pk[8 * gp + 2] = packbf(e10 * kn89.x, e11 * kn89.y);
                    pk[8 * gp + 3] = packbf(e12 * kn89.x, e13 * kn89.y);
                }
                // exp + fold key norm + pack, group B (g0+1)
                {
                    float e00 = expp(sB0[0]), e01 = expp(sB0[1]);
                    float e02 = expp(sB0[2]), e03 = expp(sB0[3]);
                    float e10 = expp(sB1[0]), e11 = expp(sB1[1]);
                    float e12 = expp(sB1[2]), e13 = expp(sB1[3]);
                    den0 += e00 + e01 + e10 + e11;
                    den1 += e02 + e03 + e12 + e13;
                    float2 kn01, kn89;
                    asm("ld.shared.v2.f32 {%0,%1}, [%2];" : "=f"(kn01.x), "=f"(kn01.y)
                        : "r"(knb + ((g0 + 1) * 16 + jq) * 4));
                    asm("ld.shared.v2.f32 {%0,%1}, [%2];" : "=f"(kn89.x), "=f"(kn89.y)
                        : "r"(knb + ((g0 + 1) * 16 + 8 + jq) * 4));
                    pk[8 * gp + 4] = packbf(e00 * kn01.x, e01 * kn01.y);
                    pk[8 * gp + 5] = packbf(e02 * kn01.x, e03 * kn01.y);
                    pk[8 * gp + 6] = packbf(e10 * kn89.x, e11 * kn89.y);
                    pk[8 * gp + 7] = packbf(e12 * kn89.x, e13 * kn89.y);
                }
            }
            // ---- V-steps for this half-phase (keys hp*64 .. hp*64+63) ----
            #pragma unroll
            for (int ki = 0; ki < 4; ki++) {
                const int kk = hp * 4 + ki;
                int vrow = kk * 16 + kg1 * 8 + klr;
                #pragma unroll
                for (int dg = 0; dg < 8; dg++) {
                    uint32_t v[4];
                    ldsm4t(v, nb + toff(vrow, 2 * dg + kg2));
                    mma16816(o[2 * dg],     &pk[4 * ki], v[0], v[1]);
                    mma16816(o[2 * dg + 1], &pk[4 * ki], v[2], v[3]);
                }
            }
        }

        __syncthreads();
        prefetch_tile(t + 2, sb, tid);
    }

    // ---- denominators: quad reduce (4 lanes per row) ----
    den0 += __shfl_xor_sync(0xffffffffu, den0, 1);
    den0 += __shfl_xor_sync(0xffffffffu, den0, 2);
    den1 += __shfl_xor_sync(0xffffffffu, den1, 1);
    den1 += __shfl_xor_sync(0xffffffffu, den1, 2);
    const float inv0 = 0.5f / den0;   // folds SCALE=-0.5
    const float inv1 = 0.5f / den1;

    const int r0 = wid * 16 + (lane >> 2);
    const size_t grow0 = (size_t)(i0 + r0) * DD;
    const size_t grow1 = grow0 + 8 * DD;

    float s10 = 0, s20 = 0, s11 = 0, s21 = 0;
    #pragma unroll
    for (int j = 0; j < 16; j++) {
        int col = 8 * j + (lane & 3) * 2;
        float2 xv0 = *(const float2*)(x + grow0 + col);
        float2 xv1 = *(const float2*)(x + grow1 + col);
        float y00 = fmaf(1.5f, xv0.x, -o[j][0] * inv0);
        float y01 = fmaf(1.5f, xv0.y, -o[j][1] * inv0);
        float y10 = fmaf(1.5f, xv1.x, -o[j][2] * inv1);
        float y11 = fmaf(1.5f, xv1.y, -o[j][3] * inv1);
        o[j][0] = y00; o[j][1] = y01; o[j][2] = y10; o[j][3] = y11;
        s10 += y00 + y01;           s11 += y10 + y11;
        s20 = fmaf(y00, y00, s20);  s20 = fmaf(y01, y01, s20);
        s21 = fmaf(y10, y10, s21);  s21 = fmaf(y11, y11, s21);
    }
    s10 += __shfl_xor_sync(0xffffffffu, s10, 1);
    s10 += __shfl_xor_sync(0xffffffffu, s10, 2);
    s20 += __shfl_xor_sync(0xffffffffu, s20, 1);
    s20 += __shfl_xor_sync(0xffffffffu, s20, 2);
    s11 += __shfl_xor_sync(0xffffffffu, s11, 1);
    s11 += __shfl_xor_sync(0xffffffffu, s11, 2);
    s21 += __shfl_xor_sync(0xffffffffu, s21, 1);
    s21 += __shfl_xor_sync(0xffffffffu, s21, 2);

    const float mu0 = s10 * (1.0f / DD);
    const float mu1 = s11 * (1.0f / DD);
    const float rs0 = rsqrtf(s20 * (1.0f / DD) - mu0 * mu0 + 1e-5f);
    const float rs1 = rsqrtf(s21 * (1.0f / DD) - mu1 * mu1 + 1e-5f);

    #pragma unroll
    for (int j = 0; j < 16; j++) {
        int col = 8 * j + (lane & 3) * 2;
        float2 gm = *(const float2*)(gamma + col);
        float2 bt = *(const float2*)(beta + col);
        float2 o0, o1;
        o0.x = fmaf((o[j][0] - mu0) * rs0, gm.x, bt.x);
        o0.y = fmaf((o[j][1] - mu0) * rs0, gm.y, bt.y);
        o1.x = fmaf((o[j][2] - mu1) * rs1, gm.x, bt.x);
        o1.y = fmaf((o[j][3] - mu1) * rs1, gm.y, bt.y);
        *(float2*)(out + grow0 + col) = o0;
        *(float2*)(out + grow1 + col) = o1;
    }
}

// ---------------------------------------------------------------------------
extern "C" void kernel_launch(void* const* d_in, const int* in_sizes, int n_in,
                              void* d_out, int out_size) {
    const float* x     = (const float*)d_in[0];
    const float* gamma = (const float*)d_in[1];
    const float* beta  = (const float*)d_in[2];
    float* out = (float*)d_out;

    prep_kernel<<<NROWS / 8, 256>>>(x);

    cudaFuncSetAttribute(attn_kernel,
                         cudaFuncAttributeMaxDynamicSharedMemorySize, SMEM_BYTES);
    attn_kernel<<<NROWS / BM, NTHREADS, SMEM_BYTES>>>(x, gamma, beta, out);
}